// round 14
// baseline (speedup 1.0000x reference)
#include <cuda_runtime.h>
#include <cstdint>

#define BS_   2
#define SEQ   2048
#define HID   1024
#define HEADS 16
#define HD    64
#define NTOK  (BS_*SEQ)   // 4096

// Scratch (allocation-free rule: __device__ globals)
__device__ float g_Q[NTOK*HID];
__device__ float g_K[NTOK*HID];
__device__ float g_V[NTOK*HID];
__device__ float g_A[NTOK*HID];

// ===========================================================================
// helpers
// ===========================================================================
__device__ __forceinline__ uint32_t smem_u32(const void* p) {
    uint32_t a;
    asm("{ .reg .u64 t; cvta.to.shared.u64 t, %1; cvt.u32.u64 %0, t; }"
        : "=r"(a) : "l"(p));
    return a;
}
__device__ __forceinline__ void cp_async16(uint32_t dst, const void* src) {
    asm volatile("cp.async.cg.shared.global [%0], [%1], 16;"
                 :: "r"(dst), "l"(src) : "memory");
}
#define CP_COMMIT() asm volatile("cp.async.commit_group;" ::: "memory")
#define CP_WAIT(n)  asm volatile("cp.async.wait_group %0;" :: "n"(n) : "memory")

// round-to-nearest fp32 -> tf32
__device__ __forceinline__ uint32_t f2tf32(float f) {
    uint32_t r;
    asm("cvt.rna.tf32.f32 %0, %1;" : "=r"(r) : "f"(f));
    return r;
}

// m16n8k8 tf32 MMA (A row-major, B col-major), fp32 accum
// A frag: a0=(gid,tg) a1=(gid+8,tg) a2=(gid,tg+4) a3=(gid+8,tg+4)
// B frag: b0=(k=tg,n=gid) b1=(k=tg+4,n=gid)
// C frag: c0=(gid,2tg) c1=(gid,2tg+1) c2=(gid+8,2tg) c3=(gid+8,2tg+1)
__device__ __forceinline__ void mma_tf32(float* c, const uint32_t* a,
                                         const uint32_t* b) {
    asm volatile(
        "mma.sync.aligned.m16n8k8.row.col.f32.tf32.tf32.f32 "
        "{%0,%1,%2,%3}, {%4,%5,%6,%7}, {%8,%9}, {%0,%1,%2,%3};"
        : "+f"(c[0]), "+f"(c[1]), "+f"(c[2]), "+f"(c[3])
        : "r"(a[0]), "r"(a[1]), "r"(a[2]), "r"(a[3]), "r"(b[0]), "r"(b[1]));
}

// ===========================================================================
// TF32 mma.sync GEMM: C[M,N] = A[M,K] * B[N,K]^T + bias   (UNCHANGED — control)
// ===========================================================================
#define BM  128
#define BN  128
#define BK  32
#define LDP (BK + 4)
#define TILE_F (BM * LDP)
#define GM_SMEM (4 * TILE_F * (int)sizeof(float))

__global__ void __launch_bounds__(256) gemm_tf32_kernel(
    const float* __restrict__ A, const float* __restrict__ B,
    const float* __restrict__ bias, float* __restrict__ C)
{
    constexpr int N = HID, K = HID;
    constexpr int NT = K / BK;
    extern __shared__ float sm[];
    float* As = sm;
    float* Bs = sm + 2 * TILE_F;

    const int tid  = threadIdx.x;
    const int wid  = tid >> 5, lane = tid & 31;
    const int wm   = wid >> 2, wn = wid & 3;
    const int gid  = lane >> 2, tg = lane & 3;
    const int brow = blockIdx.y * BM;
    const int bcol = blockIdx.x * BN;

    float acc[4][4][4];
    #pragma unroll
    for (int i = 0; i < 4; i++)
        #pragma unroll
        for (int j = 0; j < 4; j++)
            #pragma unroll
            for (int e = 0; e < 4; e++) acc[i][j][e] = 0.f;

    const uint32_t sA0 = smem_u32(As);
    const uint32_t sB0 = smem_u32(Bs);

    auto load_tile = [&](int buf, int k0) {
        const uint32_t dA = sA0 + buf * TILE_F * 4;
        const uint32_t dB = sB0 + buf * TILE_F * 4;
        #pragma unroll
        for (int i = 0; i < 4; i++) {
            int idx = tid + i * 256;
            int row = idx >> 3, c4 = idx & 7;
            cp_async16(dA + (row * LDP + c4 * 4) * 4,
                       A + (size_t)(brow + row) * K + k0 + c4 * 4);
            cp_async16(dB + (row * LDP + c4 * 4) * 4,
                       B + (size_t)(bcol + row) * K + k0 + c4 * 4);
        }
        CP_COMMIT();
    };

    load_tile(0, 0);

    for (int t = 0; t < NT; t++) {
        const int cur = t & 1;
        if (t + 1 < NT) { load_tile(1 - cur, (t + 1) * BK); CP_WAIT(1); }
        else            { CP_WAIT(0); }
        __syncthreads();

        const float* wA = As + cur * TILE_F + (wm * 64) * LDP;
        const float* wB = Bs + cur * TILE_F + (wn * 32) * LDP;

        #pragma unroll
        for (int ks = 0; ks < 4; ks++) {
            const int kb = ks * 8;
            uint32_t a[4][4], b[4][2];
            #pragma unroll
            for (int mt = 0; mt < 4; mt++) {
                const float* p = wA + (mt * 16 + gid) * LDP + kb + tg;
                a[mt][0] = f2tf32(p[0]);
                a[mt][1] = f2tf32(p[8 * LDP]);
                a[mt][2] = f2tf32(p[4]);
                a[mt][3] = f2tf32(p[8 * LDP + 4]);
            }
            #pragma unroll
            for (int nt = 0; nt < 4; nt++) {
                const float* p = wB + (nt * 8 + gid) * LDP + kb + tg;
                b[nt][0] = f2tf32(p[0]);
                b[nt][1] = f2tf32(p[4]);
            }
            #pragma unroll
            for (int mt = 0; mt < 4; mt++)
                #pragma unroll
                for (int nt = 0; nt < 4; nt++)
                    mma_tf32(acc[mt][nt], a[mt], b[nt]);
        }
        __syncthreads();
    }

    const int rbase = brow + wm * 64;
    const int cbase = bcol + wn * 32;
    #pragma unroll
    for (int mt = 0; mt < 4; mt++) {
        #pragma unroll
        for (int nt = 0; nt < 4; nt++) {
            const int r0 = rbase + mt * 16 + gid;
            const int c0 = cbase + nt * 8 + tg * 2;
            float2 bv = *(const float2*)(bias + c0);
            float2 v0 = { acc[mt][nt][0] + bv.x, acc[mt][nt][1] + bv.y };
            float2 v1 = { acc[mt][nt][2] + bv.x, acc[mt][nt][3] + bv.y };
            *(float2*)(C + (size_t)r0 * N + c0)       = v0;
            *(float2*)(C + (size_t)(r0 + 8) * N + c0) = v1;
        }
    }
}

// ===========================================================================
// Flash attention, tf32 mma.sync. 64x64 tiles, 4 warps.
// R14: Q frags register-resident (converted once); K/V stored in SMEM as
// tf32 bits (cvt at load time, raw uint32 in mainloop); P stored as tf32
// bits. Removes ~320 cvts/tile/thread + all Q LDS from the mainloop.
// ===========================================================================
#define ALD 68
#define AT_SMEM (4 * 64 * ALD * (int)sizeof(float))   // 69632B (Qs,Ks,Vs,Ps)

__global__ void __launch_bounds__(128) attn_kernel(
    const float* __restrict__ Q, const float* __restrict__ K,
    const float* __restrict__ V, float* __restrict__ O)
{
    extern __shared__ float smf[];
    float*    Qs  = smf;                         // [64][ALD] fp32 (staging only)
    uint32_t* Ksu = (uint32_t*)(smf + 64 * ALD); // [64][ALD] tf32 bits
    uint32_t* Vsu = Ksu + 64 * ALD;              // [64][ALD] tf32 bits
    uint32_t* Psu = Vsu + 64 * ALD;              // [64][ALD] tf32 bits

    const int qt = blockIdx.x, h = blockIdx.y, b = blockIdx.z;
    const int tid = threadIdx.x, wid = tid >> 5, lane = tid & 31;
    const int gid = lane >> 2, tg = lane & 3;
    const int mbase = wid * 16;

    // Stage Q tile (pre-scaled by 1/sqrt(64)) into SMEM
    const float* qbase = Q + ((size_t)(b * SEQ + qt * 64)) * HID + h * HD;
    for (int i = tid; i < 64 * 16; i += 128) {
        int r = i >> 4, c4 = i & 15;
        float4 v = *(const float4*)(qbase + (size_t)r * HID + c4 * 4);
        v.x *= 0.125f; v.y *= 0.125f; v.z *= 0.125f; v.w *= 0.125f;
        *(float4*)(Qs + r * ALD + c4 * 4) = v;
    }
    __syncthreads();

    // Convert this warp's Q fragments ONCE; keep in registers for all kt.
    uint32_t qa[8][4];
    #pragma unroll
    for (int kf = 0; kf < 8; kf++) {
        const float* pa = Qs + (mbase + gid) * ALD + kf * 8 + tg;
        qa[kf][0] = f2tf32(pa[0]);
        qa[kf][1] = f2tf32(pa[8 * ALD]);
        qa[kf][2] = f2tf32(pa[4]);
        qa[kf][3] = f2tf32(pa[8 * ALD + 4]);
    }

    float m0 = -1e30f, m1 = -1e30f, l0 = 0.f, l1 = 0.f;
    float o[8][4];
    #pragma unroll
    for (int i = 0; i < 8; i++)
        #pragma unroll
        for (int e = 0; e < 4; e++) o[i][e] = 0.f;

    for (int kt = 0; kt <= qt; kt++) {
        __syncthreads();   // all warps done with Ksu/Vsu from previous tile
        const float* kbase = K + ((size_t)(b * SEQ + kt * 64)) * HID + h * HD;
        const float* vbase = V + ((size_t)(b * SEQ + kt * 64)) * HID + h * HD;
        for (int i = tid; i < 64 * 16; i += 128) {
            int r = i >> 4, c4 = i & 15;
            float4 kv = *(const float4*)(kbase + (size_t)r * HID + c4 * 4);
            float4 vv = *(const float4*)(vbase + (size_t)r * HID + c4 * 4);
            uint4 ku = { f2tf32(kv.x), f2tf32(kv.y), f2tf32(kv.z), f2tf32(kv.w) };
            uint4 vu = { f2tf32(vv.x), f2tf32(vv.y), f2tf32(vv.z), f2tf32(vv.w) };
            *(uint4*)(Ksu + r * ALD + c4 * 4) = ku;
            *(uint4*)(Vsu + r * ALD + c4 * 4) = vu;
        }
        __syncthreads();

        // ---- S = Q * K^T  (raw tf32 bits from SMEM, Q from registers) ----
        float s[8][4];
        #pragma unroll
        for (int i = 0; i < 8; i++)
            #pragma unroll
            for (int e = 0; e < 4; e++) s[i][e] = 0.f;

        #pragma unroll
        for (int kf = 0; kf < 8; kf++) {
            const int kb = kf * 8;
            #pragma unroll
            for (int nt = 0; nt < 8; nt++) {
                const uint32_t* pb = Ksu + (nt * 8 + gid) * ALD + kb + tg;
                uint32_t bf[2] = { pb[0], pb[4] };
                mma_tf32(s[nt], qa[kf], bf);
            }
        }

        // ---- online softmax on fragment rows gid / gid+8 ----
        float mx0 = -1e30f, mx1 = -1e30f;
        #pragma unroll
        for (int nt = 0; nt < 8; nt++) {
            mx0 = fmaxf(mx0, fmaxf(s[nt][0], s[nt][1]));
            mx1 = fmaxf(mx1, fmaxf(s[nt][2], s[nt][3]));
        }
        mx0 = fmaxf(mx0, __shfl_xor_sync(0xffffffffu, mx0, 1));
        mx0 = fmaxf(mx0, __shfl_xor_sync(0xffffffffu, mx0, 2));
        mx1 = fmaxf(mx1, __shfl_xor_sync(0xffffffffu, mx1, 1));
        mx1 = fmaxf(mx1, __shfl_xor_sync(0xffffffffu, mx1, 2));

        const float mn0 = fmaxf(m0, mx0), mn1 = fmaxf(m1, mx1);
        const float cr0 = __expf(m0 - mn0), cr1 = __expf(m1 - mn1);
        float sum0 = 0.f, sum1 = 0.f;
        uint32_t* pr0 = Psu + (mbase + gid) * ALD + 2 * tg;
        uint32_t* pr1 = pr0 + 8 * ALD;
        #pragma unroll
        for (int nt = 0; nt < 8; nt++) {
            float p00 = __expf(s[nt][0] - mn0);
            float p01 = __expf(s[nt][1] - mn0);
            float p10 = __expf(s[nt][2] - mn1);
            float p11 = __expf(s[nt][3] - mn1);
            sum0 += p00 + p01;
            sum1 += p10 + p11;
            uint2 w0 = { f2tf32(p00), f2tf32(p01) };
            uint2 w1 = { f2tf32(p10), f2tf32(p11) };
            *(uint2*)(pr0 + nt * 8) = w0;
            *(uint2*)(pr1 + nt * 8) = w1;
        }
        sum0 += __shfl_xor_sync(0xffffffffu, sum0, 1);
        sum0 += __shfl_xor_sync(0xffffffffu, sum0, 2);
        sum1 += __shfl_xor_sync(0xffffffffu, sum1, 1);
        sum1 += __shfl_xor_sync(0xffffffffu, sum1, 2);

        m0 = mn0; m1 = mn1;
        l0 = l0 * cr0 + sum0;
        l1 = l1 * cr1 + sum1;
        #pragma unroll
        for (int nt = 0; nt < 8; nt++) {
            o[nt][0] *= cr0; o[nt][1] *= cr0;
            o[nt][2] *= cr1; o[nt][3] *= cr1;
        }
        __syncwarp();   // Psu rows are warp-private

        // ---- O += P * V  (raw tf32 bits) ----
        #pragma unroll
        for (int kf = 0; kf < 8; kf++) {
            const int kb = kf * 8;
            const uint32_t* pa = Psu + (mbase + gid) * ALD + kb + tg;
            uint32_t a[4] = { pa[0], pa[8 * ALD], pa[4], pa[8 * ALD + 4] };
            #pragma unroll
            for (int nt = 0; nt < 8; nt++) {
                const uint32_t* pb = Vsu + (kb + tg) * ALD + nt * 8 + gid;
                uint32_t bf[2] = { pb[0], pb[4 * ALD] };
                mma_tf32(o[nt], a, bf);
            }
        }
    }

    // ---- epilogue ----
    const float inv0 = 1.f / l0, inv1 = 1.f / l1;
    float* ob = O + ((size_t)(b * SEQ + qt * 64 + mbase)) * HID + h * HD;
    #pragma unroll
    for (int nt = 0; nt < 8; nt++) {
        const int col = nt * 8 + 2 * tg;
        *(float2*)(ob + (size_t)gid * HID + col) =
            make_float2(o[nt][0] * inv0, o[nt][1] * inv0);
        *(float2*)(ob + (size_t)(gid + 8) * HID + col) =
            make_float2(o[nt][2] * inv1, o[nt][3] * inv1);
    }
}

// ---------------------------------------------------------------------------
extern "C" void kernel_launch(void* const* d_in, const int* in_sizes, int n_in,
                              void* d_out, int out_size) {
    const float* X  = (const float*)d_in[0];
    const float* Wq = (const float*)d_in[1];
    const float* bq = (const float*)d_in[2];
    const float* Wk = (const float*)d_in[3];
    const float* bk = (const float*)d_in[4];
    const float* Wv = (const float*)d_in[5];
    const float* bv = (const float*)d_in[6];
    const float* Wo = (const float*)d_in[7];
    const float* bo = (const float*)d_in[8];
    float* out = (float*)d_out;

    float *Qp, *Kp, *Vp, *Ap;
    cudaGetSymbolAddress((void**)&Qp, g_Q);
    cudaGetSymbolAddress((void**)&Kp, g_K);
    cudaGetSymbolAddress((void**)&Vp, g_V);
    cudaGetSymbolAddress((void**)&Ap, g_A);

    cudaFuncSetAttribute(gemm_tf32_kernel,
                         cudaFuncAttributeMaxDynamicSharedMemorySize, GM_SMEM);
    cudaFuncSetAttribute(attn_kernel,
                         cudaFuncAttributeMaxDynamicSharedMemorySize, AT_SMEM);

    dim3 gg(HID / BN, NTOK / BM);  // (8, 32) = 256 CTAs
    gemm_tf32_kernel<<<gg, 256, GM_SMEM>>>(X, Wq, bq, Qp);
    gemm_tf32_kernel<<<gg, 256, GM_SMEM>>>(X, Wk, bk, Kp);
    gemm_tf32_kernel<<<gg, 256, GM_SMEM>>>(X, Wv, bv, Vp);

    attn_kernel<<<dim3(SEQ / 64, HEADS, BS_), 128, AT_SMEM>>>(Qp, Kp, Vp, Ap);

    gemm_tf32_kernel<<<gg, 256, GM_SMEM>>>(Ap, Wo, bo, out);
}